// round 3
// baseline (speedup 1.0000x reference)
#include <cuda_runtime.h>
#include <cuda_bf16.h>
#include <math.h>

// Problem dims
#define PB 64      // batch
#define PT 1024    // time
#define PE 256     // embed
#define PU 1024    // units
#define PC3 3072   // 3*U

// Recurrent kernel config
#define NBLK 128       // persistent blocks (<= SM count, 1 block/SM)
#define TILE_U 8       // u columns per block: NBLK*TILE_U == PU
#define TPB 256        // threads per block
#define KCH 64         // k-chunk staged in smem

// ---------------------------------------------------------------------------
// scratch: xp[t][b][3U] input projections (written by GEMM1, read by scan)
// ---------------------------------------------------------------------------
__device__ float g_xp[(size_t)PT * PB * PC3];

// grid barrier state
__device__ unsigned g_bar_count = 0;
__device__ unsigned g_bar_gen = 0;

__device__ __forceinline__ void grid_barrier(unsigned nb) {
    __syncthreads();
    if (threadIdx.x == 0) {
        __threadfence();
        unsigned g = *((volatile unsigned*)&g_bar_gen);
        unsigned prev = atomicAdd(&g_bar_count, 1u);
        if (prev == nb - 1u) {
            atomicExch(&g_bar_count, 0u);
            __threadfence();
            atomicAdd(&g_bar_gen, 1u);
        } else {
            while (*((volatile unsigned*)&g_bar_gen) == g) { }
            __threadfence();
        }
    }
    __syncthreads();
}

// ---------------------------------------------------------------------------
// Kernel 1: xp[r][n] = emb[x(b,t)][:] @ W_in[:,n] + b_in[n],  r = t*B + b
// Classic SMEM-tiled SGEMM: BM=128, BN=128, BK=16, 256 threads, 8x8/thread.
// ---------------------------------------------------------------------------
__global__ __launch_bounds__(256) void k_inproj(
    const int* __restrict__ x,
    const float* __restrict__ emb,
    const float* __restrict__ Win,
    const float* __restrict__ bin,
    float* __restrict__ xp)
{
    __shared__ float As[16][132];   // A^T tile, padded
    __shared__ float Bs[16][128];
    __shared__ int rowIdx[128];

    const int tid = threadIdx.x;
    const int m0 = blockIdx.y * 128;
    const int n0 = blockIdx.x * 128;

    if (tid < 128) {
        int m = m0 + tid;                 // m = t*64 + b
        rowIdx[tid] = x[(size_t)(m & 63) * PT + (m >> 6)];
    }
    __syncthreads();

    float acc[8][8];
#pragma unroll
    for (int i = 0; i < 8; i++)
#pragma unroll
        for (int j = 0; j < 8; j++) acc[i][j] = 0.f;

    const int mo = (tid >> 4) * 4;   // 0..60
    const int no = (tid & 15) * 4;   // 0..60

    for (int kt = 0; kt < PE; kt += 16) {
        // load A tile (gathered rows from embedding table), store transposed
#pragma unroll
        for (int i = 0; i < 2; i++) {
            int fl = tid + i * 256;
            int am = fl >> 2, ac = fl & 3;
            const float4 v = *(const float4*)(emb + (size_t)rowIdx[am] * PE + kt + ac * 4);
            As[ac * 4 + 0][am] = v.x;
            As[ac * 4 + 1][am] = v.y;
            As[ac * 4 + 2][am] = v.z;
            As[ac * 4 + 3][am] = v.w;
        }
        // load B tile (coalesced)
#pragma unroll
        for (int i = 0; i < 2; i++) {
            int fl = tid + i * 256;
            int bk = fl >> 5, bn = fl & 31;
            *(float4*)&Bs[bk][bn * 4] =
                *(const float4*)(Win + (size_t)(kt + bk) * PC3 + n0 + bn * 4);
        }
        __syncthreads();

#pragma unroll
        for (int k = 0; k < 16; k++) {
            float a[8], b[8];
            *(float4*)&a[0] = *(const float4*)&As[k][mo];
            *(float4*)&a[4] = *(const float4*)&As[k][mo + 64];
            *(float4*)&b[0] = *(const float4*)&Bs[k][no];
            *(float4*)&b[4] = *(const float4*)&Bs[k][no + 64];
#pragma unroll
            for (int i = 0; i < 8; i++)
#pragma unroll
                for (int j = 0; j < 8; j++)
                    acc[i][j] += a[i] * b[j];
        }
        __syncthreads();
    }

    const float4 bv0 = *(const float4*)(bin + n0 + no);
    const float4 bv1 = *(const float4*)(bin + n0 + no + 64);
#pragma unroll
    for (int i = 0; i < 8; i++) {
        int mrow = m0 + ((i < 4) ? (mo + i) : (mo + 64 + i - 4));
        float4 r0, r1;
        r0.x = acc[i][0] + bv0.x; r0.y = acc[i][1] + bv0.y;
        r0.z = acc[i][2] + bv0.z; r0.w = acc[i][3] + bv0.w;
        r1.x = acc[i][4] + bv1.x; r1.y = acc[i][5] + bv1.y;
        r1.z = acc[i][6] + bv1.z; r1.w = acc[i][7] + bv1.w;
        *(float4*)(xp + (size_t)mrow * PC3 + n0 + no)      = r0;
        *(float4*)(xp + (size_t)mrow * PC3 + n0 + no + 64) = r1;
    }
}

// ---------------------------------------------------------------------------
// Kernel 2: persistent GRU scan.
// 128 blocks x 256 threads; block p owns u in [p*8, p*8+8).
// W_rec slice (8 u x 3 gates, interleaved z,r,h,pad per u) cached in SMEM once.
// Per step: stage h_{t-1} chunk [64k x 64b] in SMEM, accumulate 3 dots per
// (b,u), apply gates, write out[b][t][u], grid barrier.
// ---------------------------------------------------------------------------
__device__ __forceinline__ float sigmoidf_(float v) {
    return 1.0f / (1.0f + expf(-v));
}

__global__ __launch_bounds__(TPB, 1) void k_gru(
    const float* __restrict__ xp,
    const float* __restrict__ h0,
    const float* __restrict__ Wrec,
    const float* __restrict__ brec,
    float* __restrict__ out,
    float* __restrict__ hlast)
{
    extern __shared__ float sm[];
    float* Ws = sm;                                   // [1024][TILE_U] float4 = 128KB
    float* hs = sm + (size_t)1024 * TILE_U * 4;       // [KCH][68]        = 17KB
    float* os = hs + (size_t)KCH * 68;                // [64][TILE_U]     = 2KB

    const int tid  = threadIdx.x;
    const int lane = tid & 31;
    const int uu   = tid >> 5;            // warp id = local u (0..7)
    const int ubase = blockIdx.x * TILE_U;
    const int u = ubase + uu;

    // cache W_rec columns (z,r,h for each local u) in SMEM, once
    float4* Ws4 = (float4*)Ws;
    for (int idx = tid; idx < 1024 * TILE_U; idx += TPB) {
        int k = idx / TILE_U;
        int j = idx - k * TILE_U;
        float4 w;
        w.x = Wrec[(size_t)k * PC3 +            (ubase + j)];
        w.y = Wrec[(size_t)k * PC3 + PU     +   (ubase + j)];
        w.z = Wrec[(size_t)k * PC3 + 2 * PU +   (ubase + j)];
        w.w = 0.f;
        Ws4[idx] = w;
    }
    const float brz = brec[u];
    const float brr = brec[PU + u];
    const float brh = brec[2 * PU + u];
    __syncthreads();

    const int b0 = 2 * lane;
    const int b1 = b0 + 1;

    for (int t = 0; t < PT; t++) {
        float az0 = 0.f, ar0 = 0.f, ah0 = 0.f;
        float az1 = 0.f, ar1 = 0.f, ah1 = 0.f;

#pragma unroll 1
        for (int kc = 0; kc < PU; kc += KCH) {
            __syncthreads();
            // stage h_{t-1}[b][kc+kk] -> hs[kk][b] (coalesced global reads)
#pragma unroll
            for (int i = 0; i < (64 * KCH) / TPB; i++) {
                int idx = tid + i * TPB;
                int kk = idx & (KCH - 1);
                int b  = idx >> 6;
                float v = (t == 0)
                    ? h0[(size_t)b * PU + kc + kk]
                    : out[((size_t)b * PT + (t - 1)) * PU + kc + kk];
                hs[kk * 68 + b] = v;
            }
            __syncthreads();

            const float4* Wp = Ws4 + (size_t)kc * TILE_U + uu;
#pragma unroll
            for (int kk = 0; kk < KCH; kk++) {
                float2 hv = *(const float2*)&hs[kk * 68 + b0];
                float4 w  = Wp[(size_t)kk * TILE_U];
                az0 += hv.x * w.x; ar0 += hv.x * w.y; ah0 += hv.x * w.z;
                az1 += hv.y * w.x; ar1 += hv.y * w.y; ah1 += hv.y * w.z;
            }
        }

        // gate epilogue for (b0,u) and (b1,u)
        {
            const float* xb0 = xp + ((size_t)t * PB + b0) * PC3 + u;
            const float* xb1 = xp + ((size_t)t * PB + b1) * PC3 + u;
            float hp0 = (t == 0) ? h0[(size_t)b0 * PU + u]
                                 : out[((size_t)b0 * PT + (t - 1)) * PU + u];
            float hp1 = (t == 0) ? h0[(size_t)b1 * PU + u]
                                 : out[((size_t)b1 * PT + (t - 1)) * PU + u];

            float z0 = sigmoidf_(xb0[0]      + az0 + brz);
            float r0 = sigmoidf_(xb0[PU]     + ar0 + brr);
            float c0 = tanhf(xb0[2 * PU] + r0 * (ah0 + brh));
            float hn0 = z0 * hp0 + (1.f - z0) * c0;

            float z1 = sigmoidf_(xb1[0]      + az1 + brz);
            float r1 = sigmoidf_(xb1[PU]     + ar1 + brr);
            float c1 = tanhf(xb1[2 * PU] + r1 * (ah1 + brh));
            float hn1 = z1 * hp1 + (1.f - z1) * c1;

            os[b0 * TILE_U + uu] = hn0;
            os[b1 * TILE_U + uu] = hn1;
        }
        __syncthreads();

        // coalesced 16B writes of this block's u-slice for all 64 b
        if (tid < 128) {
            int b = tid >> 1, half = tid & 1;
            float4 v = ((const float4*)os)[b * 2 + half];
            *(float4*)(out + ((size_t)b * PT + t) * PU + ubase + half * 4) = v;
            if (t == PT - 1 && hlast != nullptr) {
                *(float4*)(hlast + (size_t)b * PU + ubase + half * 4) = v;
            }
        }

        grid_barrier(NBLK);
    }
}

// ---------------------------------------------------------------------------
// launch
// ---------------------------------------------------------------------------
extern "C" void kernel_launch(void* const* d_in, const int* in_sizes, int n_in,
                              void* d_out, int out_size)
{
    const int*   x       = (const int*)  d_in[0];
    const float* initial = (const float*)d_in[1];
    const float* emb     = (const float*)d_in[2];
    const float* Win     = (const float*)d_in[3];
    const float* Wrec    = (const float*)d_in[4];
    const float* bin     = (const float*)d_in[5];
    const float* brec    = (const float*)d_in[6];

    float* out = (float*)d_out;
    float* hlast = nullptr;
    const long long n_outputs = (long long)PB * PT * PU;
    if ((long long)out_size >= n_outputs + (long long)PB * PU) {
        hlast = out + (size_t)n_outputs;
    }

    float* xp = nullptr;
    cudaGetSymbolAddress((void**)&xp, g_xp);

    // GEMM1: embedding gather + input projection
    dim3 g1(PC3 / 128, (PT * PB) / 128);
    k_inproj<<<g1, 256>>>(x, emb, Win, bin, xp);

    // GRU scan (persistent, grid barrier per step)
    const int smem = (1024 * TILE_U * 4 + KCH * 68 + 64 * TILE_U) * (int)sizeof(float);
    cudaFuncSetAttribute(k_gru, cudaFuncAttributeMaxDynamicSharedMemorySize, smem);
    k_gru<<<NBLK, TPB, smem>>>(xp, initial, Wrec, brec, out, hlast);
}